// round 9
// baseline (speedup 1.0000x reference)
#include <cuda_runtime.h>
#include <cuda_bf16.h>

// Neighbor list (cutoff^2 = 25.0, exclude self), per-row ascending compaction
// into K=32 slots padded with -1; zero cell_indices [n,K,3]; scalar max count.
//
// DTYPE LESSON (rounds 1-7): rel_err was nan every round. int32 data normed in
// float cannot give nan; float32-read CAN (int -1 == 0xFFFFFFFF == NaN). So the
// __output__ dtype is float32: write to_idx as floats, pad with -1.0f, zeros
// (bit-identical either way), scalar max as float via int-aliased atomicMax.
//
// Layout (float32 elements): [0,nK) to_idx | [nK,4nK) zeros | [4nK] max
// resolved from out_size with K=32 prior:
//   S % (4n) == 1 -> full tuple + scalar     (S = 4nK+1)
//   S == 32*n     -> to_idx only, K=32
//   else retry with S/4 (byte-count reading)
// n from positions: elements mode (any in_size==1) -> P/3, else P/12.

#define TILE    2048
#define WARPS   16
#define THREADS (WARPS * 32)

__global__ void fill_kernel(int* __restrict__ out, long long begin, long long end)
{
    const long long stride = (long long)gridDim.x * blockDim.x;
    for (long long i = begin + (long long)blockIdx.x * blockDim.x + threadIdx.x;
         i < end; i += stride)
        out[i] = 0;                       // 0 bits == 0.0f == (int)0
}

__global__ __launch_bounds__(THREADS)
void nbr_kernel(const float* __restrict__ pos,
                float*       __restrict__ out,
                int n, int K, long long scalarIdx)
{
    const int tid  = threadIdx.x;
    const int lane = tid & 31;
    const int wid  = tid >> 5;
    const int row  = blockIdx.x * WARPS + wid;

    __shared__ float4 tile[TILE];
    __shared__ int    wmax[WARPS];

    const bool valid = (row < n);                  // warp-uniform
    float rx = 0.f, ry = 0.f, rz = 0.f;
    if (valid) {
        rx = pos[3 * row + 0];
        ry = pos[3 * row + 1];
        rz = pos[3 * row + 2];
    }

    int cnt = 0;
    for (int t0 = 0; t0 < n; t0 += TILE) {
        const int m = min(TILE, n - t0);
        __syncthreads();
        for (int i = tid; i < m; i += THREADS) {
            const int j = t0 + i;
            tile[i] = make_float4(pos[3*j], pos[3*j+1], pos[3*j+2], 0.f);
        }
        __syncthreads();

        if (valid) {
            for (int b = 0; b < m; b += 32) {      // warp-uniform trip count
                const int c = b + lane;
                const int j = t0 + c;
                const float4 p = tile[c];
                const float dx = rx - p.x;
                const float dy = ry - p.y;
                const float dz = rz - p.z;
                const float r2 = fmaf(dx, dx, fmaf(dy, dy, dz * dz));
                const bool pred = (c < m) & (r2 <= 25.0f) & (j != row);
                const unsigned bm = __ballot_sync(0xffffffffu, pred);
                if (pred) {
                    const int slot = cnt + __popc(bm & ((1u << lane) - 1u));
                    if (slot < K)
                        out[(long long)row * K + slot] = (float)j;   // FLOAT index
                }
                cnt += __popc(bm);                 // unclipped, for max
            }
        }
    }

    if (valid) {
        for (int s = cnt + lane; s < K; s += 32)
            out[(long long)row * K + s] = -1.0f;   // FLOAT padding (not NaN bits)
    }

    if (lane == 0) wmax[wid] = valid ? cnt : 0;
    __syncthreads();
    if (wid == 0 && scalarIdx >= 0) {
        int v = (lane < WARPS) ? wmax[lane] : 0;
        #pragma unroll
        for (int o = 8; o > 0; o >>= 1)
            v = max(v, __shfl_down_sync(0xffffffffu, v, o));
        if (lane == 0) {
            // float atomicMax via int alias (valid: both operands >= 0.0f,
            // slot pre-zeroed by fill_kernel; IEEE order == int order for >=0)
            const float fv = (float)v;
            atomicMax((int*)(out + scalarIdx), __float_as_int(fv));
        }
    }
}

extern "C" void kernel_launch(void* const* d_in, const int* in_sizes, int n_in,
                              void* d_out, int out_size)
{
    // positions = largest input
    const float* pos = nullptr;
    long long P = 0;
    bool haveSize1 = false;
    for (int i = 0; i < n_in; i++) {
        if ((long long)in_sizes[i] > P) { P = in_sizes[i]; pos = (const float*)d_in[i]; }
        if (in_sizes[i] == 1) haveSize1 = true;
    }
    float* out = (float*)d_out;
    const long long S = (long long)out_size;
    if (!pos || P < 3 || S <= 0) return;

    // n: elements mode if any size-1 input exists (scalar max_neighbours),
    // else byte mode.
    long long n = 0;
    if (haveSize1 && (P % 3) == 0)      n = P / 3;
    else if ((P % 12) == 0)             n = P / 12;
    else if ((P % 3) == 0)              n = P / 3;
    if (n <= 0) return;

    // layout resolution with K=32 prior; try S as elements, then as bytes.
    long long K = 0, scalarIdx = -1, totalElems = 0;
    for (int pass = 0; pass < 2 && K == 0; pass++) {
        long long s = (pass == 0) ? S : ((S % 4 == 0) ? S / 4 : -1);
        if (s <= 0) continue;
        if ((s - 1) > 0 && (s - 1) % (4 * n) == 0) {          // 4nK+1
            long long k = (s - 1) / (4 * n);
            if (k >= 1 && k <= 1024) { K = k; scalarIdx = 4*n*k; totalElems = s; break; }
        }
        if (s == 32 * n) { K = 32; scalarIdx = -1; totalElems = s; break; }  // to_idx only
        if (s % (4 * n) == 0) {                                // 4nK, no scalar
            long long k = s / (4 * n);
            if (k >= 1 && k <= 1024) { K = k; scalarIdx = -1; totalElems = s; break; }
        }
        if ((s - 1) > 0 && (s - 1) % n == 0) {                 // nK+1
            long long k = (s - 1) / n;
            if (k >= 1 && k <= 1024) { K = k; scalarIdx = n*k; totalElems = s; break; }
        }
    }
    if (K == 0) return;   // refuse to launch with unresolved geometry

    const long long nK = n * K;
    if (totalElems > nK)
        fill_kernel<<<256, 512>>>((int*)d_out, nK, totalElems);

    const int grid = (int)((n + WARPS - 1) / WARPS);
    nbr_kernel<<<grid, THREADS>>>(pos, out, (int)n, (int)K, scalarIdx);
}

// round 10
// speedup vs baseline: 2.9180x; 2.9180x over previous
#include <cuda_runtime.h>
#include <cuda_bf16.h>

// Neighbor list (cutoff^2 = 25.0, exclude self), per-row ascending compaction
// into K slots padded with -1; zero cell_indices [n,K,3]; scalar max count.
// Output dtype: FLOAT32 (lesson of rounds 1-8). Layout (elements):
//   [0,nK) to_idx | [nK,4nK) zeros | [4nK] actual_max
//
// Fast path: uniform cell grid (16^3 cells of edge 5.0 = cutoff), counting
// sort, then warp-per-row gather over the 3x3x3 neighborhood (9 contiguous
// x-segments), ballot-compaction into a 64-slot buffer, warp bitonic sort to
// restore ascending original-index order. ~150x fewer distance tests than
// the O(N^2) brute force (kept as fallback for oversized inputs).

#define WARPS   16
#define THREADS (WARPS * 32)
#define TILE    2048

#define NCELL   16
#define NCELL3  (NCELL * NCELL * NCELL)
#define CELLINV 0.2f          /* 1 / 5.0 */
#define MAX_N   32768
#define CAP     64            /* per-row hit buffer */

__device__ int    g_count[NCELL3];
__device__ int    g_start[NCELL3 + 1];
__device__ int    g_rank[MAX_N];
__device__ float4 g_sorted[MAX_N];

__device__ __forceinline__ int cell_of(float x, float y, float z) {
    int cx = min(max(__float2int_rd(x * CELLINV), 0), NCELL - 1);
    int cy = min(max(__float2int_rd(y * CELLINV), 0), NCELL - 1);
    int cz = min(max(__float2int_rd(z * CELLINV), 0), NCELL - 1);
    return (cz * NCELL + cy) * NCELL + cx;
}

__global__ void zero_kernel(float* __restrict__ out, long long scalarIdx)
{
    const int i = blockIdx.x * blockDim.x + threadIdx.x;
    if (i < NCELL3) g_count[i] = 0;
    if (i == 0 && scalarIdx >= 0) out[scalarIdx] = 0.0f;
}

__global__ void histo_kernel(const float* __restrict__ pos, int n)
{
    const int i = blockIdx.x * blockDim.x + threadIdx.x;
    if (i >= n) return;
    const int c = cell_of(pos[3*i], pos[3*i+1], pos[3*i+2]);
    g_rank[i] = atomicAdd(&g_count[c], 1);
}

__global__ __launch_bounds__(1024)
void scan_kernel(int n)
{
    __shared__ int s[1024];
    const int t = threadIdx.x;
    const int base = t * 4;
    const int c0 = g_count[base + 0];
    const int c1 = g_count[base + 1];
    const int c2 = g_count[base + 2];
    const int c3 = g_count[base + 3];
    const int p  = c0 + c1 + c2 + c3;
    s[t] = p;
    __syncthreads();
    for (int off = 1; off < 1024; off <<= 1) {
        int v = (t >= off) ? s[t - off] : 0;
        __syncthreads();
        s[t] += v;
        __syncthreads();
    }
    int e = s[t] - p;                 // exclusive prefix of this thread's group
    g_start[base + 0] = e;
    g_start[base + 1] = e + c0;
    g_start[base + 2] = e + c0 + c1;
    g_start[base + 3] = e + c0 + c1 + c2;
    if (t == 1023) g_start[NCELL3] = s[1023];   // == n
}

__global__ void scatter_kernel(const float* __restrict__ pos, int n)
{
    const int i = blockIdx.x * blockDim.x + threadIdx.x;
    if (i >= n) return;
    const float x = pos[3*i], y = pos[3*i+1], z = pos[3*i+2];
    const int c = cell_of(x, y, z);
    g_sorted[g_start[c] + g_rank[i]] = make_float4(x, y, z, (float)i);
}

__device__ __forceinline__ int cmpex(int v, int j, bool up, int lane)
{
    const int o = __shfl_xor_sync(0xffffffffu, v, j);
    const bool lower = (lane & j) == 0;
    return (lower == up) ? min(v, o) : max(v, o);
}

__global__ __launch_bounds__(THREADS)
void nbr_cell_kernel(const float* __restrict__ pos,
                     float*       __restrict__ out,
                     int n, int K, long long scalarIdx)
{
    const int tid  = threadIdx.x;
    const int lane = tid & 31;
    const int wid  = tid >> 5;
    const int row  = blockIdx.x * WARPS + wid;

    __shared__ int hits[WARPS][CAP];
    __shared__ int wmax[WARPS];

    const bool valid = (row < n);                  // warp-uniform
    int cnt = 0;
    int v0 = 0x7FFFFFFF, v1 = 0x7FFFFFFF;

    if (valid) {
        const float rx = pos[3*row], ry = pos[3*row+1], rz = pos[3*row+2];
        const int cx = min(max(__float2int_rd(rx * CELLINV), 0), NCELL-1);
        const int cy = min(max(__float2int_rd(ry * CELLINV), 0), NCELL-1);
        const int cz = min(max(__float2int_rd(rz * CELLINV), 0), NCELL-1);
        const int x0 = max(cx - 1, 0), x1 = min(cx + 1, NCELL-1);

        for (int dz = -1; dz <= 1; dz++) {
            const int cz2 = cz + dz;
            if (cz2 < 0 || cz2 >= NCELL) continue;         // warp-uniform
            for (int dy = -1; dy <= 1; dy++) {
                const int cy2 = cy + dy;
                if (cy2 < 0 || cy2 >= NCELL) continue;     // warp-uniform
                const int rb = (cz2 * NCELL + cy2) * NCELL;
                const int s  = g_start[rb + x0];
                const int e  = g_start[rb + x1 + 1];
                for (int b = s; b < e; b += 32) {          // warp-uniform bounds
                    const int idx = b + lane;
                    bool pred = false;
                    int  j = 0;
                    if (idx < e) {
                        const float4 p = g_sorted[idx];
                        const float dx = rx - p.x;
                        const float dyv = ry - p.y;
                        const float dzv = rz - p.z;
                        const float r2 = fmaf(dx, dx, fmaf(dyv, dyv, dzv*dzv));
                        j = (int)p.w;
                        pred = (r2 <= 25.0f) & (j != row);
                    }
                    const unsigned bm = __ballot_sync(0xffffffffu, pred);
                    if (pred) {
                        const int slot = cnt + __popc(bm & ((1u << lane) - 1u));
                        if (slot < CAP) hits[wid][slot] = j;
                    }
                    cnt += __popc(bm);                     // unclipped, for max
                }
            }
        }

        // load hit buffer (sentinel INT_MAX beyond cnt)
        const int m = min(cnt, CAP);
        v0 = (lane      < m) ? hits[wid][lane]      : 0x7FFFFFFF;
        v1 = (lane + 32 < m) ? hits[wid][lane + 32] : 0x7FFFFFFF;

        // bitonic sort of 64 elements: lane holds indices {lane, lane+32}
        #pragma unroll
        for (int k = 2; k <= 32; k <<= 1) {
            #pragma unroll
            for (int j = k >> 1; j > 0; j >>= 1) {
                v0 = cmpex(v0, j, (lane & k) == 0,          lane);
                v1 = cmpex(v1, j, ((lane + 32) & k) == 0,   lane);
            }
        }
        { // k = 64: j=32 is the intra-lane exchange, then j=16..1 ascending
            const int lo = min(v0, v1), hi = max(v0, v1);
            v0 = lo; v1 = hi;
            #pragma unroll
            for (int j = 16; j > 0; j >>= 1) {
                v0 = cmpex(v0, j, true, lane);
                v1 = cmpex(v1, j, true, lane);
            }
        }

        // emit to_idx (K <= 32 on this path)
        if (lane < K)
            out[(long long)row * K + lane] =
                (v0 == 0x7FFFFFFF) ? -1.0f : (float)v0;

        // fused zero of this row's cell_indices chunk [nK + row*3K, +3K)
        const long long cbase = (long long)n * K + (long long)row * 3 * K;
        for (int t = lane; t < 3 * K; t += 32)
            out[cbase + t] = 0.0f;
    }

    if (lane == 0) wmax[wid] = valid ? cnt : 0;
    __syncthreads();
    if (wid == 0 && scalarIdx >= 0) {
        int v = (lane < WARPS) ? wmax[lane] : 0;
        #pragma unroll
        for (int o = 8; o > 0; o >>= 1)
            v = max(v, __shfl_down_sync(0xffffffffu, v, o));
        if (lane == 0)
            atomicMax((int*)(out + scalarIdx), __float_as_int((float)v));
    }
}

// ---------------- fallback: brute force (oversized n or K) ----------------
__global__ void fill_kernel(float* __restrict__ out, long long b, long long e)
{
    const long long stride = (long long)gridDim.x * blockDim.x;
    for (long long i = b + (long long)blockIdx.x * blockDim.x + threadIdx.x;
         i < e; i += stride)
        out[i] = 0.0f;
}

__global__ __launch_bounds__(THREADS)
void nbr_brute_kernel(const float* __restrict__ pos,
                      float*       __restrict__ out,
                      int n, int K, long long scalarIdx)
{
    const int tid  = threadIdx.x;
    const int lane = tid & 31;
    const int wid  = tid >> 5;
    const int row  = blockIdx.x * WARPS + wid;
    __shared__ float4 tile[TILE];
    __shared__ int    wmax[WARPS];
    const bool valid = (row < n);
    float rx = 0.f, ry = 0.f, rz = 0.f;
    if (valid) { rx = pos[3*row]; ry = pos[3*row+1]; rz = pos[3*row+2]; }
    int cnt = 0;
    for (int t0 = 0; t0 < n; t0 += TILE) {
        const int m = min(TILE, n - t0);
        __syncthreads();
        for (int i = tid; i < m; i += THREADS) {
            const int j = t0 + i;
            tile[i] = make_float4(pos[3*j], pos[3*j+1], pos[3*j+2], 0.f);
        }
        __syncthreads();
        if (valid) {
            for (int b = 0; b < m; b += 32) {
                const int c = b + lane;
                const int j = t0 + c;
                const float4 p = tile[c];
                const float dx = rx-p.x, dy = ry-p.y, dz = rz-p.z;
                const float r2 = fmaf(dx,dx, fmaf(dy,dy, dz*dz));
                const bool pred = (c < m) & (r2 <= 25.0f) & (j != row);
                const unsigned bm = __ballot_sync(0xffffffffu, pred);
                if (pred) {
                    const int slot = cnt + __popc(bm & ((1u << lane) - 1u));
                    if (slot < K) out[(long long)row*K + slot] = (float)j;
                }
                cnt += __popc(bm);
            }
        }
    }
    if (valid)
        for (int s = cnt + lane; s < K; s += 32)
            out[(long long)row*K + s] = -1.0f;
    if (lane == 0) wmax[wid] = valid ? cnt : 0;
    __syncthreads();
    if (wid == 0 && scalarIdx >= 0) {
        int v = (lane < WARPS) ? wmax[lane] : 0;
        #pragma unroll
        for (int o = 8; o > 0; o >>= 1)
            v = max(v, __shfl_down_sync(0xffffffffu, v, o));
        if (lane == 0)
            atomicMax((int*)(out + scalarIdx), __float_as_int((float)v));
    }
}

extern "C" void kernel_launch(void* const* d_in, const int* in_sizes, int n_in,
                              void* d_out, int out_size)
{
    // positions = largest input (geometry resolution identical to round 9)
    const float* pos = nullptr;
    long long P = 0;
    bool haveSize1 = false;
    for (int i = 0; i < n_in; i++) {
        if ((long long)in_sizes[i] > P) { P = in_sizes[i]; pos = (const float*)d_in[i]; }
        if (in_sizes[i] == 1) haveSize1 = true;
    }
    float* out = (float*)d_out;
    const long long S = (long long)out_size;
    if (!pos || P < 3 || S <= 0) return;

    long long n = 0;
    if (haveSize1 && (P % 3) == 0)      n = P / 3;
    else if ((P % 12) == 0)             n = P / 12;
    else if ((P % 3) == 0)              n = P / 3;
    if (n <= 0) return;

    long long K = 0, scalarIdx = -1, totalElems = 0;
    for (int pass = 0; pass < 2 && K == 0; pass++) {
        long long s = (pass == 0) ? S : ((S % 4 == 0) ? S / 4 : -1);
        if (s <= 0) continue;
        if ((s - 1) > 0 && (s - 1) % (4 * n) == 0) {
            long long k = (s - 1) / (4 * n);
            if (k >= 1 && k <= 1024) { K = k; scalarIdx = 4*n*k; totalElems = s; break; }
        }
        if (s == 32 * n) { K = 32; scalarIdx = -1; totalElems = s; break; }
        if (s % (4 * n) == 0) {
            long long k = s / (4 * n);
            if (k >= 1 && k <= 1024) { K = k; scalarIdx = -1; totalElems = s; break; }
        }
        if ((s - 1) > 0 && (s - 1) % n == 0) {
            long long k = (s - 1) / n;
            if (k >= 1 && k <= 1024) { K = k; scalarIdx = n*k; totalElems = s; break; }
        }
    }
    if (K == 0) return;

    const long long nK = n * K;
    const int grid = (int)((n + WARPS - 1) / WARPS);

    if (n <= MAX_N && K <= 32) {
        // fast path: cell grid. cell_indices zeros fused into main kernel;
        // [4nK, totalElems) beyond scalar handled: only scalar slot exists.
        zero_kernel<<<(NCELL3 + 255) / 256, 256>>>(out, scalarIdx);
        histo_kernel<<<(int)((n + 255) / 256), 256>>>(pos, (int)n);
        scan_kernel<<<1, 1024>>>((int)n);
        scatter_kernel<<<(int)((n + 255) / 256), 256>>>(pos, (int)n);
        nbr_cell_kernel<<<grid, THREADS>>>(pos, out, (int)n, (int)K, scalarIdx);
    } else {
        if (totalElems > nK)
            fill_kernel<<<256, 512>>>(out, nK, totalElems);
        nbr_brute_kernel<<<grid, THREADS>>>(pos, out, (int)n, (int)K, scalarIdx);
    }
}